// round 1
// baseline (speedup 1.0000x reference)
#include <cuda_runtime.h>
#include <math.h>

#define B_    4
#define CIN   64
#define COUT  64
#define H_    128
#define W_    128
#define HW_   (H_*W_)
#define K2_   9

// Scratch (allocation-free rule: __device__ globals)
__device__ float g_dy[B_*K2_*HW_];
__device__ float g_dx[B_*K2_*HW_];
__device__ float g_mask[B_*K2_*HW_];
__device__ float g_wt[K2_*CIN*COUT];   // [k][c][o]

// ---------------------------------------------------------------------------
// Weight transpose: weight[o][c][k] -> g_wt[k][c][o]
// ---------------------------------------------------------------------------
__global__ void wt_kernel(const float* __restrict__ w) {
    int i = blockIdx.x * 256 + threadIdx.x;
    if (i < COUT*CIN*K2_) {
        int k = i % K2_;
        int c = (i / K2_) % CIN;
        int o = i / (K2_*CIN);
        g_wt[(k*CIN + c)*COUT + o] = w[i];
    }
}

// ---------------------------------------------------------------------------
// Offset/mask conv: om = conv3x3(x, om_weight) + om_bias  (27 out channels)
// Block = 2 rows x 128 cols, 128 threads; each thread -> 2 vertically adjacent
// pixels (reuses each smem weight load for 2 FFMAs). Weights staged in smem
// in two 32-channel halves to stay under the 48KB static smem limit.
// ---------------------------------------------------------------------------
__global__ __launch_bounds__(128) void om_kernel(
    const float* __restrict__ x,
    const float* __restrict__ omw,
    const float* __restrict__ omb)
{
    __shared__ float ws[32*9*27];   // [c_local][j][o], 31104 B
    int t  = threadIdx.x;
    int b  = blockIdx.x >> 6;
    int hp = blockIdx.x & 63;
    int h0 = hp * 2;
    int w  = t;                     // 0..127

    float acc0[27], acc1[27];
    #pragma unroll
    for (int o = 0; o < 27; o++) { acc0[o] = 0.f; acc1[o] = 0.f; }

    for (int cb = 0; cb < 2; cb++) {
        __syncthreads();
        for (int i = t; i < 32*9*27; i += 128) {
            int o  = i % 27;
            int j  = (i / 27) % 9;
            int cl = i / 243;
            ws[i] = omw[(o*CIN + (cb*32 + cl))*9 + j];
        }
        __syncthreads();

        for (int cl = 0; cl < 32; cl++) {
            const float* xc = x + (size_t)(b*CIN + cb*32 + cl) * HW_;
            float xv[4][3];
            #pragma unroll
            for (int rr = 0; rr < 4; rr++) {
                int row = h0 - 1 + rr;
                #pragma unroll
                for (int cc = 0; cc < 3; cc++) {
                    int col = w - 1 + cc;
                    bool ok = (row >= 0) && (row < H_) && (col >= 0) && (col < W_);
                    xv[rr][cc] = ok ? xc[row*W_ + col] : 0.f;
                }
            }
            #pragma unroll
            for (int j = 0; j < 9; j++) {
                float a0 = xv[j/3    ][j%3];
                float a1 = xv[j/3 + 1][j%3];
                #pragma unroll
                for (int o = 0; o < 27; o++) {
                    float wv = ws[cl*243 + j*27 + o];
                    acc0[o] += wv * a0;
                    acc1[o] += wv * a1;
                }
            }
        }
    }

    // Route channels: dy[k]=om[2k], dx[k]=om[2k+1] (k<9), mask[k]=sigmoid(om[18+k])
    int pix = h0*W_ + w;
    #pragma unroll
    for (int o = 0; o < 27; o++) {
        float v0 = acc0[o] + omb[o];
        float v1 = acc1[o] + omb[o];
        if (o < 18) {
            int kk = o >> 1;
            float* dst = (o & 1) ? g_dx : g_dy;
            int base = (b*K2_ + kk)*HW_;
            dst[base + pix]      = v0;
            dst[base + pix + W_] = v1;
        } else {
            int base = (b*K2_ + (o - 18))*HW_;
            g_mask[base + pix]      = 1.f / (1.f + expf(-v0));
            g_mask[base + pix + W_] = 1.f / (1.f + expf(-v1));
        }
    }
}

// ---------------------------------------------------------------------------
// Deformable conv main kernel.
// Block = (b, h) row: 128 pixels x 64 Cout. 128 threads.
// Per k: stage bilinear samples (x mask) into smem [64c][128p], then
// register-tiled GEMM: thread tile 8 Cout x 8 pixels via float4 smem loads.
// Split-halves mapping keeps LDS.128 conflict-free.
// smem = 16KB weights + 32KB samples = 48KB exactly.
// ---------------------------------------------------------------------------
__global__ __launch_bounds__(128) void deform_kernel(
    const float* __restrict__ x,
    const float* __restrict__ bias,
    float* __restrict__ out)
{
    __shared__ float ws[CIN*COUT];    // [c][o]  16KB
    __shared__ float samp[CIN*W_];    // [c][p]  32KB

    int t  = threadIdx.x;
    int b  = blockIdx.x >> 7;
    int h  = blockIdx.x & 127;
    int ty = t >> 4;     // 0..7
    int tx = t & 15;     // 0..15
    const float* xb = x + (size_t)b*CIN*HW_;

    float acc[8][8];
    #pragma unroll
    for (int i = 0; i < 8; i++)
        #pragma unroll
        for (int j = 0; j < 8; j++)
            acc[i][j] = 0.f;

    int offidx = b*K2_*HW_ + h*W_ + t;

    for (int k = 0; k < K2_; k++) {
        __syncthreads();   // previous GEMM done before overwriting smem

        // Stage weight slice [c][o] for this k
        for (int i = t; i < CIN*COUT; i += 128)
            ws[i] = g_wt[k*CIN*COUT + i];

        // ---- Sampling: thread t handles pixel w = t ----
        float dyv = g_dy[offidx + k*HW_];
        float dxv = g_dx[offidx + k*HW_];
        float mk  = g_mask[offidx + k*HW_];
        float py = dyv + (float)(k/3 + h - 1);
        float px = dxv + (float)(k%3 + t - 1);
        float y0f = floorf(py), x0f = floorf(px);
        float wy = py - y0f,   wx = px - x0f;
        int y0 = (int)y0f, x0i = (int)x0f;
        int y1 = y0 + 1,   x1  = x0i + 1;
        float vy0 = (y0  >= 0 && y0  < H_) ? 1.f : 0.f;
        float vy1 = (y1  >= 0 && y1  < H_) ? 1.f : 0.f;
        float vx0 = (x0i >= 0 && x0i < W_) ? 1.f : 0.f;
        float vx1 = (x1  >= 0 && x1  < W_) ? 1.f : 0.f;
        // fold mask + validity into corner weights
        float w00 = (1.f-wy)*(1.f-wx) * vy0*vx0 * mk;
        float w01 = (1.f-wy)*wx       * vy0*vx1 * mk;
        float w10 = wy*(1.f-wx)       * vy1*vx0 * mk;
        float w11 = wy*wx             * vy1*vx1 * mk;
        int iy0 = min(max(y0, 0), H_-1), iy1 = min(max(y1, 0), H_-1);
        int ix0 = min(max(x0i,0), W_-1), ix1 = min(max(x1, 0), W_-1);
        int i00 = iy0*W_ + ix0, i01 = iy0*W_ + ix1;
        int i10 = iy1*W_ + ix0, i11 = iy1*W_ + ix1;

        #pragma unroll 4
        for (int c = 0; c < CIN; c++) {
            const float* xc = xb + c*HW_;
            samp[c*W_ + t] = w00*xc[i00] + w01*xc[i01] + w10*xc[i10] + w11*xc[i11];
        }
        __syncthreads();

        // ---- GEMM: acc[8o][8p] += W[c][o] * samp[c][p] ----
        const float4* ws4 = (const float4*)ws;
        const float4* sp4 = (const float4*)samp;
        #pragma unroll 8
        for (int c = 0; c < CIN; c++) {
            float4 w0 = ws4[c*16 + ty];        // o = ty*4 .. +3
            float4 w1 = ws4[c*16 + 8 + ty];    // o = 32+ty*4 .. +3
            float4 s0 = sp4[c*32 + tx];        // p = tx*4 .. +3
            float4 s1 = sp4[c*32 + 16 + tx];   // p = 64+tx*4 .. +3
            float wv[8] = {w0.x,w0.y,w0.z,w0.w, w1.x,w1.y,w1.z,w1.w};
            float sv[8] = {s0.x,s0.y,s0.z,s0.w, s1.x,s1.y,s1.z,s1.w};
            #pragma unroll
            for (int i = 0; i < 8; i++)
                #pragma unroll
                for (int j = 0; j < 8; j++)
                    acc[i][j] += wv[i] * sv[j];
        }
    }

    // Epilogue
    #pragma unroll
    for (int i = 0; i < 8; i++) {
        int o = (i < 4) ? (ty*4 + i) : (32 + ty*4 + (i - 4));
        float bo = bias[o];
        float* op = out + (size_t)(b*COUT + o)*HW_ + h*W_;
        #pragma unroll
        for (int j = 0; j < 8; j++) {
            int p = (j < 4) ? (tx*4 + j) : (64 + tx*4 + (j - 4));
            op[p] = acc[i][j] + bo;
        }
    }
}

// ---------------------------------------------------------------------------
extern "C" void kernel_launch(void* const* d_in, const int* in_sizes, int n_in,
                              void* d_out, int out_size) {
    const float* x      = (const float*)d_in[0];
    const float* weight = (const float*)d_in[1];
    const float* bias   = (const float*)d_in[2];
    const float* omw    = (const float*)d_in[3];
    const float* omb    = (const float*)d_in[4];
    float* out = (float*)d_out;

    wt_kernel<<<(COUT*CIN*K2_ + 255)/256, 256>>>(weight);
    om_kernel<<<B_*(H_/2), 128>>>(x, omw, omb);
    deform_kernel<<<B_*H_, 128>>>(x, bias, out);
}